// round 11
// baseline (speedup 1.0000x reference)
#include <cuda_runtime.h>
#include <cuda_fp16.h>
#include <cstdint>

#define BATCH 64
#define NB    64
#define RANK  4
#define SEQ   4096

// sqrt(log2(e)) — folds natural-exp into a single ex2.approx
#define SQRT_LOG2E 1.2011224087864498f

#define NMLP  128            // MLP blocks (wave-1 resident, use barriers)
#define NHT   2048           // h_t blocks
#define NTILE 16384          // warp tiles: BATCH * SEQ/16

#define KS1 4
#define KS2 8
#define KS3 16
#define OMSZ (BATCH * NB * RANK * 2)   // floats per omega partial

// ---------------------------------------------------------------------------
// Scratch (device globals; no allocation allowed)
// ---------------------------------------------------------------------------
__device__ __align__(16) float  g_h1p[KS1 * BATCH * 512];
__device__ __align__(16) float  g_h2p[KS2 * BATCH * 1024];
__device__ __align__(16) float  g_omp[KS3 * OMSZ];
__device__ __align__(16) float2 g_oms[BATCH * NB * RANK];   // final omega
__device__ __align__(16) uint4  g_ht [NTILE * 128];         // h_t fragments, 32 MB
__device__ unsigned g_bars[4];                               // monotonic barriers

// ---------------------------------------------------------------------------
// Replay-safe monotonic barrier among P co-resident blocks (counter never
// reset; each use consumes exactly P increments, so replays stay aligned).
// ---------------------------------------------------------------------------
__device__ __forceinline__ void sysbar(int i, unsigned P)
{
    __syncthreads();
    if (threadIdx.x == 0) {
        __threadfence();
        const unsigned old = atomicAdd(&g_bars[i], 1u);
        const unsigned target = old - (old % P) + P;
        while (*((volatile unsigned*)&g_bars[i]) < target) __nanosleep(32);
        __threadfence();
    }
    __syncthreads();
}

// ---------------------------------------------------------------------------
// GEMM tile (R5-proven): 64 rows x 64 cols, 256 threads, f32x2 packed
// accumulators, depth-2 prefetch over double-buffered 8-k smem chunks.
// SRC: 0 = Ain param, 1 = g_h1p (sum NPART + relu), 2 = g_h2p (sum + relu)
// DST: 0 = g_h1p[z] (pre-relu), 1 = g_h2p[z], 2 = packed omega partial
// ---------------------------------------------------------------------------
template <int K, int N, int KS, int SRC, int NPART, int DST>
__device__ void gemm_tile(float (&sW)[2][8][64], float (&sA)[2][8][64],
                          const float* __restrict__ Ain,
                          const float* __restrict__ W,
                          const float* __restrict__ bias, int j0, int z)
{
    constexpr int KC  = K / KS;
    constexpr int NCH = KC / 8;
    const int tid = threadIdx.x;
    const int tx  = tid & 15;
    const int ty  = tid >> 4;
    const int k0  = z * KC;

    const bool isW = tid < 128;
    const int w_kk = tid >> 4;
    const int w_c4 = (tid & 15) * 4;
    const int a_i  = tid - 128;
    const int a_b  = a_i >> 1;
    const int a_kq = (a_i & 1) * 4;

    auto load_chunk = [&](int kc) -> float4 {
        if (isW)
            return *(const float4*)(W + (size_t)(k0 + kc + w_kk) * N + j0 + w_c4);
        float4 av;
        if (SRC == 0) {
            av = *(const float4*)(Ain + a_b * K + k0 + kc + a_kq);
        } else {
            const float* base = (SRC == 1) ? g_h1p : g_h2p;
            const float* p0 = base + a_b * K + k0 + kc + a_kq;
            av = *(const float4*)p0;
            #pragma unroll
            for (int p = 1; p < NPART; p++) {
                const float4 pv = *(const float4*)(p0 + p * (BATCH * K));
                av.x += pv.x; av.y += pv.y; av.z += pv.z; av.w += pv.w;
            }
            av.x = fmaxf(av.x, 0.f); av.y = fmaxf(av.y, 0.f);
            av.z = fmaxf(av.z, 0.f); av.w = fmaxf(av.w, 0.f);
        }
        return av;
    };
    auto store_chunk = [&](int buf, float4 v) {
        if (isW) {
            *(float4*)(&sW[buf][w_kk][w_c4]) = v;
        } else {
            sA[buf][a_kq + 0][a_b] = v.x;
            sA[buf][a_kq + 1][a_b] = v.y;
            sA[buf][a_kq + 2][a_b] = v.z;
            sA[buf][a_kq + 3][a_b] = v.w;
        }
    };

    unsigned long long acc2[4][2];
    #pragma unroll
    for (int r = 0; r < 4; r++) { acc2[r][0] = 0ull; acc2[r][1] = 0ull; }

    float4 f0 = load_chunk(0);
    store_chunk(0, f0);
    float4 f1;
    if (NCH > 1) f1 = load_chunk(8);
    __syncthreads();

    for (int c = 0; c < NCH; c++) {
        float4 f2;
        if (c + 2 < NCH) f2 = load_chunk((c + 2) * 8);

        const int buf = c & 1;
        #pragma unroll
        for (int kk = 0; kk < 8; kk++) {
            const ulonglong2 wq = *(const ulonglong2*)(&sW[buf][kk][tx * 4]);
            const float4 av = *(const float4*)(&sA[buf][kk][ty * 4]);
            const float aa[4] = {av.x, av.y, av.z, av.w};
            #pragma unroll
            for (int r = 0; r < 4; r++) {
                unsigned long long ap;
                asm("mov.b64 %0, {%1, %1};" : "=l"(ap) : "f"(aa[r]));
                asm("fma.rn.f32x2 %0, %1, %2, %0;"
                    : "+l"(acc2[r][0]) : "l"(ap), "l"(wq.x));
                asm("fma.rn.f32x2 %0, %1, %2, %0;"
                    : "+l"(acc2[r][1]) : "l"(ap), "l"(wq.y));
            }
        }

        if (c + 1 < NCH) store_chunk((c + 1) & 1, f1);
        __syncthreads();
        f1 = f2;
    }

    float o[4][4];
    #pragma unroll
    for (int r = 0; r < 4; r++) {
        asm("mov.b64 {%0, %1}, %2;" : "=f"(o[r][0]), "=f"(o[r][1]) : "l"(acc2[r][0]));
        asm("mov.b64 {%0, %1}, %2;" : "=f"(o[r][2]), "=f"(o[r][3]) : "l"(acc2[r][1]));
    }
    const int j = j0 + tx * 4;
    if (z == 0) {
        const float4 bv = *(const float4*)(bias + j);
        #pragma unroll
        for (int r = 0; r < 4; r++) {
            o[r][0] += bv.x; o[r][1] += bv.y; o[r][2] += bv.z; o[r][3] += bv.w;
        }
    }
    #pragma unroll
    for (int r = 0; r < 4; r++) {
        const int b = ty * 4 + r;
        if (DST == 0) {
            *(float4*)(g_h1p + z * (BATCH * 512) + b * 512 + j) =
                make_float4(o[r][0], o[r][1], o[r][2], o[r][3]);
        } else if (DST == 1) {
            *(float4*)(g_h2p + z * (BATCH * 1024) + b * 1024 + j) =
                make_float4(o[r][0], o[r][1], o[r][2], o[r][3]);
        } else {
            const int side = (j >= 256) ? 1 : 0;
            const int n    = (j - side * 256) >> 2;
            float* dst = g_omp + z * OMSZ + ((b * NB + n) * RANK) * 2 + side;
            dst[0] = o[r][0]; dst[2] = o[r][1];
            dst[4] = o[r][2]; dst[6] = o[r][3];
        }
    }
}

// ---------------------------------------------------------------------------
// h_t evaluation: one fma.rn.f32x2 gives {u, w}, then ex2 + cos + mul.
// s_bp per n: float4(a2, beta, -a2*mu, gamma).
// ---------------------------------------------------------------------------
__device__ __forceinline__ float ht_eval(unsigned long long tp, ulonglong2 q)
{
    unsigned long long uw;
    asm("fma.rn.f32x2 %0, %1, %2, %3;" : "=l"(uw) : "l"(tp), "l"(q.x), "l"(q.y));
    float u, w;
    asm("mov.b64 {%0, %1}, %2;" : "=f"(u), "=f"(w) : "l"(uw));
    const float nv = -u * u;
    float e, c;
    asm("ex2.approx.f32 %0, %1;" : "=f"(e) : "f"(nv));
    asm("cos.approx.f32 %0, %1;" : "=f"(c) : "f"(w));
    return e * c;
}

// ---------------------------------------------------------------------------
// Kernel A: fused MLP (blocks 0..NMLP-1, barrier-synced) + h_t fragment
// production (blocks NMLP.., fp16, MMA A-fragment order) — concurrent.
// ---------------------------------------------------------------------------
__global__ void __launch_bounds__(256, 2)
fused_a(const float* __restrict__ f,  const float* __restrict__ t,
        const float* __restrict__ W1, const float* __restrict__ b1,
        const float* __restrict__ W2, const float* __restrict__ b2,
        const float* __restrict__ W3, const float* __restrict__ b3,
        const float* __restrict__ mu, const float* __restrict__ alpha,
        const float* __restrict__ beta, const float* __restrict__ gamma)
{
    __shared__ __align__(16) float  sW[2][8][64];
    __shared__ __align__(16) float  sA[2][8][64];
    __shared__ __align__(16) float4 s_bp[NB];

    const int bid = blockIdx.x;
    const int tid = threadIdx.x;

    if (bid < NMLP) {
        // ---------------- fused MLP ----------------
        if (bid < 8 * KS1)   // 32 tiles: j0 x z
            gemm_tile<128, 512, KS1, 0, 1, 0>(sW, sA, f, W1, b1,
                                              (bid & 7) * 64, bid >> 3);
        sysbar(0, NMLP);
        // 16 col-tiles x KS2=8 = 128 units
        gemm_tile<512, 1024, KS2, 1, KS1, 1>(sW, sA, nullptr, W2, b2,
                                             (bid & 15) * 64, bid >> 4);
        sysbar(1, NMLP);
        // 8 col-tiles x KS3=16 = 128 units
        gemm_tile<1024, 512, KS3, 2, KS2, 2>(sW, sA, nullptr, W3, b3,
                                             (bid & 7) * 64, bid >> 3);
        sysbar(2, NMLP);
        if (bid < 32) {   // omega reduce: 8192 float4 over 32*256 threads
            const float4* src = (const float4*)g_omp;
            float4* dst = (float4*)g_oms;
            const int e = bid * 256 + tid;
            float4 a = src[e];
            #pragma unroll
            for (int p = 1; p < KS3; p++) {
                const float4 v = src[p * (OMSZ / 4) + e];
                a.x += v.x; a.y += v.y; a.z += v.z; a.w += v.w;
            }
            dst[e] = a;
        }
    } else {
        // ---------------- h_t fragments ----------------
        const int warp = tid >> 5;
        const int lane = tid & 31;
        const int gid  = lane >> 2;
        const int tig  = lane & 3;

        if (tid < NB) {
            const float a2 = alpha[tid] * SQRT_LOG2E;
            s_bp[tid] = make_float4(a2, beta[tid], -a2 * mu[tid], gamma[tid]);
        }
        __syncthreads();

        const int g  = (bid - NMLP) * 8 + warp;   // warp tile 0..16383
        const int b  = g >> 8;
        const int s0 = (g & 255) * 16;
        const float tv0 = t[(size_t)b * SEQ + s0 + gid];
        const float tv1 = t[(size_t)b * SEQ + s0 + gid + 8];
        unsigned long long tp0, tp1;
        asm("mov.b64 %0, {%1, %1};" : "=l"(tp0) : "f"(tv0));
        asm("mov.b64 %0, {%1, %1};" : "=l"(tp1) : "f"(tv1));

        const ulonglong2* bq = (const ulonglong2*)s_bp;

        #pragma unroll
        for (int kc = 0; kc < 4; kc++) {
            const int n0 = kc * 16 + tig * 2;
            const float e00 = ht_eval(tp0, bq[n0]);
            const float e01 = ht_eval(tp0, bq[n0 + 1]);
            const float e10 = ht_eval(tp1, bq[n0]);
            const float e11 = ht_eval(tp1, bq[n0 + 1]);
            const float e02 = ht_eval(tp0, bq[n0 + 8]);
            const float e03 = ht_eval(tp0, bq[n0 + 9]);
            const float e12 = ht_eval(tp1, bq[n0 + 8]);
            const float e13 = ht_eval(tp1, bq[n0 + 9]);
            __half2 A0 = __floats2half2_rn(e00, e01);
            __half2 A1 = __floats2half2_rn(e10, e11);
            __half2 A2 = __floats2half2_rn(e02, e03);
            __half2 A3 = __floats2half2_rn(e12, e13);
            g_ht[(size_t)(g * 4 + kc) * 32 + lane] =
                make_uint4(*(unsigned*)&A0, *(unsigned*)&A1,
                           *(unsigned*)&A2, *(unsigned*)&A3);
        }
    }
}

// ---------------------------------------------------------------------------
// Kernel B: projection. grid(8, BATCH), 256 threads; each warp does 4 tiles
// (amortizing the omega fragment build). Omega as fp16 hi+lo split -> fp32-
// accurate; h fragments are coalesced uint4 loads in exact MMA layout.
// ---------------------------------------------------------------------------
__global__ __launch_bounds__(256)
void proj_b(float* __restrict__ out)
{
    __shared__ __align__(16) float2 s_om[NB * RANK];

    const int tid  = threadIdx.x;
    const int b    = blockIdx.y;
    const int warp = tid >> 5;
    const int lane = tid & 31;
    const int gid  = lane >> 2;
    const int tig  = lane & 3;

    s_om[tid] = g_oms[b * 256 + tid];
    __syncthreads();

    auto omega_at = [&](int k, int c) -> float {
        const float2 v = s_om[k * 4 + (c & 3)];
        return (c < 4) ? v.x : v.y;
    };

    unsigned bhi[4][2], blo[4][2];
    #pragma unroll
    for (int kc = 0; kc < 4; kc++) {
        #pragma unroll
        for (int h = 0; h < 2; h++) {
            const int k0 = kc * 16 + tig * 2 + h * 8;
            const float w0 = omega_at(k0, gid);
            const float w1 = omega_at(k0 + 1, gid);
            __half2 hh = __floats2half2_rn(w0, w1);
            const float2 hf = __half22float2(hh);
            __half2 ll = __floats2half2_rn(w0 - hf.x, w1 - hf.y);
            bhi[kc][h] = *(unsigned*)&hh;
            blo[kc][h] = *(unsigned*)&ll;
        }
    }

    float* ob = out + (size_t)b * (2 * SEQ * RANK);
    const int t0 = (blockIdx.x * 8 + warp) * 4;   // 4 consecutive tiles

    #pragma unroll
    for (int i = 0; i < 4; i++) {
        const int tile = t0 + i;            // 0..255 within b
        const int g = b * 256 + tile;
        float c0 = 0.f, c1 = 0.f, c2 = 0.f, c3 = 0.f;

        #pragma unroll
        for (int kc = 0; kc < 4; kc++) {
            const uint4 av = g_ht[(size_t)(g * 4 + kc) * 32 + lane];
            asm("mma.sync.aligned.m16n8k16.row.col.f32.f16.f16.f32 "
                "{%0,%1,%2,%3}, {%4,%5,%6,%7}, {%8,%9}, {%0,%1,%2,%3};"
                : "+f"(c0), "+f"(c1), "+f"(c2), "+f"(c3)
                : "r"(av.x), "r"(av.y), "r"(av.z), "r"(av.w),
                  "r"(bhi[kc][0]), "r"(bhi[kc][1]));
            asm("mma.sync.aligned.m16n8k16.row.col.f32.f16.f16.f32 "
                "{%0,%1,%2,%3}, {%4,%5,%6,%7}, {%8,%9}, {%0,%1,%2,%3};"
                : "+f"(c0), "+f"(c1), "+f"(c2), "+f"(c3)
                : "r"(av.x), "r"(av.y), "r"(av.z), "r"(av.w),
                  "r"(blo[kc][0]), "r"(blo[kc][1]));
        }

        const int r0 = tile * 16 + gid;
        const int r1 = r0 + 8;
        *(float2*)(ob + (size_t)r0 * 8 + tig * 2) = make_float2(c0, c1);
        *(float2*)(ob + (size_t)r1 * 8 + tig * 2) = make_float2(c2, c3);
    }
}

// ---------------------------------------------------------------------------
// Launch
// ---------------------------------------------------------------------------
extern "C" void kernel_launch(void* const* d_in, const int* in_sizes, int n_in,
                              void* d_out, int out_size)
{
    const float* f     = (const float*)d_in[0];
    const float* t     = (const float*)d_in[1];
    const float* W1    = (const float*)d_in[2];
    const float* b1    = (const float*)d_in[3];
    const float* W2    = (const float*)d_in[4];
    const float* b2    = (const float*)d_in[5];
    const float* W3    = (const float*)d_in[6];
    const float* b3    = (const float*)d_in[7];
    const float* mu    = (const float*)d_in[8];
    const float* alpha = (const float*)d_in[9];
    const float* beta  = (const float*)d_in[10];
    const float* gamma = (const float*)d_in[11];
    float* out = (float*)d_out;

    fused_a<<<NMLP + NHT, 256>>>(f, t, W1, b1, W2, b2, W3, b3,
                                 mu, alpha, beta, gamma);
    proj_b<<<dim3(8, BATCH), 256>>>(out);
}